// round 2
// baseline (speedup 1.0000x reference)
#include <cuda_runtime.h>
#include <math.h>

// ---------------------------------------------------------------------------
// Waveletnet: 4-level Haar wavelet U-Net, fp32 direct implementation.
// Shapes: x (16,3,256,256) -> y (16,2,256,256)
// ---------------------------------------------------------------------------

#define NB 16

// Static scratch (allocation-free rule: __device__ globals)
__device__ float g_c1 [4194304];   // 16x16x128x128
__device__ float g_c2 [4194304];   // 16x64x64x64
__device__ float g_c3 [4194304];   // 16x256x32x32
__device__ float g_w4 [4194304];   // 16x1024x16x16
__device__ float g_t0 [4194304];
__device__ float g_t1 [4194304];
__device__ float g_big[8388608];   // concat buffers (iw4/iw3/iw2 are all 8.39M)
__device__ float g_wsw[9437184];   // standardized weights scratch (max 1024*1024*9)

// ---------------------------------------------------------------------------
// Weight standardization: per output filter, mean over K elems, unbiased std.
// wout = (w - mean) / (sqrt(ss/(K-1)) + 1e-5)
// ---------------------------------------------------------------------------
__global__ void ws_kernel(const float* __restrict__ w, float* __restrict__ out, int K)
{
    int f = blockIdx.x;
    const float* wf = w + (size_t)f * K;
    __shared__ float red[256];
    float s = 0.f;
    for (int i = threadIdx.x; i < K; i += 256) s += wf[i];
    red[threadIdx.x] = s; __syncthreads();
    for (int o = 128; o; o >>= 1) {
        if (threadIdx.x < o) red[threadIdx.x] += red[threadIdx.x + o];
        __syncthreads();
    }
    float mean = red[0] / (float)K;
    __syncthreads();
    float ss = 0.f;
    for (int i = threadIdx.x; i < K; i += 256) { float d = wf[i] - mean; ss += d * d; }
    red[threadIdx.x] = ss; __syncthreads();
    for (int o = 128; o; o >>= 1) {
        if (threadIdx.x < o) red[threadIdx.x] += red[threadIdx.x + o];
        __syncthreads();
    }
    float inv = 1.0f / (sqrtf(red[0] / (float)(K - 1)) + 1e-5f);
    for (int i = threadIdx.x; i < K; i += 256)
        out[(size_t)f * K + i] = (wf[i] - mean) * inv;
}

// ---------------------------------------------------------------------------
// GroupNorm, in place. One block per (n, group).
// ---------------------------------------------------------------------------
__global__ void gn_kernel(float* __restrict__ x, const float* __restrict__ gamma,
                          const float* __restrict__ beta, int C, int HW, int G)
{
    int n = blockIdx.x / G, grp = blockIdx.x % G;
    int cpg = C / G;
    int len = cpg * HW;
    size_t base = ((size_t)n * C + (size_t)grp * cpg) * HW;
    __shared__ float r1[256], r2[256];
    float s = 0.f, ss = 0.f;
    for (int i = threadIdx.x; i < len; i += 256) {
        float v = x[base + i];
        s += v; ss += v * v;
    }
    r1[threadIdx.x] = s; r2[threadIdx.x] = ss; __syncthreads();
    for (int o = 128; o; o >>= 1) {
        if (threadIdx.x < o) { r1[threadIdx.x] += r1[threadIdx.x + o]; r2[threadIdx.x] += r2[threadIdx.x + o]; }
        __syncthreads();
    }
    float mean = r1[0] / (float)len;
    float var  = r2[0] / (float)len - mean * mean;
    float inv  = rsqrtf(var + 1e-5f);
    for (int i = threadIdx.x; i < len; i += 256) {
        int c = grp * cpg + i / HW;
        x[base + i] = (x[base + i] - mean) * inv * gamma[c] + beta[c];
    }
}

// ---------------------------------------------------------------------------
// Haar wavelet forward: (N,C,H,W) -> (N,4C,H/2,W/2), detail remap (r+1)/2
// ---------------------------------------------------------------------------
__global__ void wt_kernel(const float* __restrict__ in, float* __restrict__ out,
                          int C, int H, int W)
{
    int h2 = H >> 1, w2 = W >> 1;
    size_t total = (size_t)NB * C * h2 * w2;
    for (size_t idx = (size_t)blockIdx.x * blockDim.x + threadIdx.x; idx < total;
         idx += (size_t)gridDim.x * blockDim.x) {
        int j = (int)(idx % w2); size_t t = idx / w2;
        int i = (int)(t % h2); t /= h2;
        int c = (int)(t % C); int n = (int)(t / C);
        const float* p = in + ((size_t)(n * C + c) * H + 2 * i) * W + 2 * j;
        float a = p[0], b = p[1], cc = p[W], d = p[W + 1];
        size_t cs = (size_t)h2 * w2;
        size_t ob = (((size_t)n * 4 * C + 4 * c) * h2 + i) * w2 + j;
        out[ob]          = 0.25f * (a + b + cc + d);
        out[ob + cs]     = 0.25f * (a + b - cc - d) + 0.5f;
        out[ob + 2 * cs] = 0.25f * (a - b + cc - d) + 0.5f;
        out[ob + 3 * cs] = 0.25f * (a - b - cc + d) + 0.5f;
    }
}

// ---------------------------------------------------------------------------
// Haar inverse: input (N,4C,h,w), details remap 2v-1, scatter to 2x2 blocks.
// Writes into output buffer with channel offset (for concat) and total Cdst.
// ---------------------------------------------------------------------------
__global__ void iwt_kernel(const float* __restrict__ in, float* __restrict__ out,
                           int C, int h, int w, int c_off, int Cdst)
{
    size_t total = (size_t)NB * C * h * w;
    for (size_t idx = (size_t)blockIdx.x * blockDim.x + threadIdx.x; idx < total;
         idx += (size_t)gridDim.x * blockDim.x) {
        int j = (int)(idx % w); size_t t = idx / w;
        int i = (int)(t % h); t /= h;
        int c = (int)(t % C); int n = (int)(t / C);
        size_t cs = (size_t)h * w;
        size_t ib = (((size_t)n * 4 * C + 4 * c) * h + i) * w + j;
        float s0 = in[ib];
        float s1 = 2.f * in[ib + cs]     - 1.f;
        float s2 = 2.f * in[ib + 2 * cs] - 1.f;
        float s3 = 2.f * in[ib + 3 * cs] - 1.f;
        float* q = out + (((size_t)n * Cdst + c_off + c) * 2 * h + 2 * i) * 2 * w + 2 * j;
        q[0]         = s0 + 0.5f * ( s1 + s2 + s3);
        q[1]         = s0 + 0.5f * ( s1 - s2 - s3);
        q[2 * w]     = s0 + 0.5f * (-s1 + s2 - s3);
        q[2 * w + 1] = s0 + 0.5f * (-s1 - s2 + s3);
    }
}

// ---------------------------------------------------------------------------
// Channel-offset copy (for skip concatenation)
// ---------------------------------------------------------------------------
__global__ void copy_ch_kernel(const float* __restrict__ src, float* __restrict__ dst,
                               int C, int HW, int Cdst, int c_off)
{
    size_t total = (size_t)NB * C * HW;
    for (size_t idx = (size_t)blockIdx.x * blockDim.x + threadIdx.x; idx < total;
         idx += (size_t)gridDim.x * blockDim.x) {
        int p = (int)(idx % HW); size_t t = idx / HW;
        int c = (int)(t % C); int n = (int)(t / C);
        dst[((size_t)n * Cdst + c_off + c) * HW + p] = src[idx];
    }
}

// ---------------------------------------------------------------------------
// Direct 3x3 conv, pad 1, NCHW fp32. 16x16 spatial tile x 32 out-channels per
// block. 256 threads: 4 co-groups x 64 pixel-threads; each thread: 8 co x 4 px
// accumulators (32 FMA per 6 shared loads). Fused bias / skip / lrelu.
// ---------------------------------------------------------------------------
__global__ __launch_bounds__(256) void conv3x3_kernel(
    const float* __restrict__ in, const float* __restrict__ wgt,
    const float* __restrict__ bias, const float* __restrict__ skip,
    float* __restrict__ out, int Cin, int Cout, int H, int W, int do_lrelu)
{
    __shared__ __align__(16) float s_in[4][18][18];
    __shared__ __align__(16) float s_w[4][9][32];

    int tiles_x = W >> 4;
    int tx0 = (blockIdx.x % tiles_x) << 4;
    int ty0 = (blockIdx.x / tiles_x) << 4;
    int co_base = blockIdx.y << 5;
    int n = blockIdx.z;
    int tx = threadIdx.x;
    int cog8 = (tx >> 6) << 3;      // 0,8,16,24
    int pid  = tx & 63;
    int prow = pid >> 2;            // 0..15
    int pcol = (pid & 3) << 2;      // 0,4,8,12

    float acc[8][4];
#pragma unroll
    for (int r = 0; r < 8; r++)
#pragma unroll
        for (int p = 0; p < 4; p++) acc[r][p] = 0.f;

    for (int cc = 0; cc < Cin; cc += 4) {
        // weights -> smem [ci][tap][co]
        for (int idx = tx; idx < 4 * 9 * 32; idx += 256) {
            int co = idx & 31;
            int tap = (idx >> 5) % 9;
            int ci = (idx >> 5) / 9;
            float v = 0.f;
            if (co_base + co < Cout && cc + ci < Cin)
                v = wgt[((size_t)(co_base + co) * Cin + cc + ci) * 9 + tap];
            s_w[ci][tap][co] = v;
        }
        // input tile + halo -> smem
        for (int idx = tx; idx < 4 * 18 * 18; idx += 256) {
            int ix = idx % 18; int t = idx / 18;
            int iy = t % 18;  int ci = t / 18;
            int gy = ty0 + iy - 1, gx = tx0 + ix - 1;
            float v = 0.f;
            if (cc + ci < Cin && gy >= 0 && gy < H && gx >= 0 && gx < W)
                v = in[((size_t)(n * Cin + cc + ci) * H + gy) * W + gx];
            s_in[ci][iy][ix] = v;
        }
        __syncthreads();

#pragma unroll
        for (int ci = 0; ci < 4; ci++) {
#pragma unroll
            for (int dy = 0; dy < 3; dy++) {
#pragma unroll
                for (int dx = 0; dx < 3; dx++) {
                    float xv[4];
#pragma unroll
                    for (int p = 0; p < 4; p++) xv[p] = s_in[ci][prow + dy][pcol + dx + p];
                    const float* wp = &s_w[ci][dy * 3 + dx][cog8];
                    float4 wa = *reinterpret_cast<const float4*>(wp);
                    float4 wb = *reinterpret_cast<const float4*>(wp + 4);
                    float wv[8] = {wa.x, wa.y, wa.z, wa.w, wb.x, wb.y, wb.z, wb.w};
#pragma unroll
                    for (int r = 0; r < 8; r++)
#pragma unroll
                        for (int p = 0; p < 4; p++) acc[r][p] = fmaf(wv[r], xv[p], acc[r][p]);
                }
            }
        }
        __syncthreads();
    }

    int oy = ty0 + prow;
#pragma unroll
    for (int r = 0; r < 8; r++) {
        int co = co_base + cog8 + r;
        if (co < Cout) {
            float b = bias ? bias[co] : 0.f;
            size_t ob = ((size_t)(n * Cout + co) * H + oy) * W + tx0 + pcol;
#pragma unroll
            for (int p = 0; p < 4; p++) {
                float v = acc[r][p] + b;
                if (skip) v += skip[ob + p];
                if (do_lrelu) v = v > 0.f ? v : 0.2f * v;
                out[ob + p] = v;
            }
        }
    }
}

// ---------------------------------------------------------------------------
// Final 1x1 conv: (N,3,HW) x (2,3) -> (N,2,HW), no bias.
// ---------------------------------------------------------------------------
__global__ void final_kernel(const float* __restrict__ in, const float* __restrict__ w,
                             float* __restrict__ out, int HW)
{
    size_t total = (size_t)NB * HW;
    for (size_t idx = (size_t)blockIdx.x * blockDim.x + threadIdx.x; idx < total;
         idx += (size_t)gridDim.x * blockDim.x) {
        int p = (int)(idx % HW); int n = (int)(idx / HW);
        const float* ip = in + (size_t)n * 3 * HW + p;
        float x0 = ip[0], x1 = ip[HW], x2 = ip[2 * HW];
        float* op = out + (size_t)n * 2 * HW + p;
        op[0]  = w[0] * x0 + w[1] * x1 + w[2] * x2;
        op[HW] = w[3] * x0 + w[4] * x1 + w[5] * x2;
    }
}

// ---------------------------------------------------------------------------
// Host orchestration
// ---------------------------------------------------------------------------
static inline int blocks_for(size_t n) { return (int)((n + 255) / 256); }

extern "C" void kernel_launch(void* const* d_in, const int* in_sizes, int n_in,
                              void* d_out, int out_size)
{
    const float* x        = (const float*)d_in[0];
    const float* conv1_w  = (const float*)d_in[1];  const float* conv1_b  = (const float*)d_in[2];
    const float* conv2_w  = (const float*)d_in[3];  const float* conv2_b  = (const float*)d_in[4];
    const float* conv3_w  = (const float*)d_in[5];  const float* conv3_b  = (const float*)d_in[6];
    const float* conv4_w  = (const float*)d_in[7];  const float* conv4_b  = (const float*)d_in[8];
    const float* convd1_w = (const float*)d_in[9];  const float* convd1_b = (const float*)d_in[10];
    const float* convd2_w = (const float*)d_in[11]; const float* convd2_b = (const float*)d_in[12];
    const float* convd3_w = (const float*)d_in[13]; const float* convd3_b = (const float*)d_in[14];
    const float* convd4_w = (const float*)d_in[15]; const float* convd4_b = (const float*)d_in[16];
    const float* final_w  = (const float*)d_in[17];
    const float* gn1_w = (const float*)d_in[18]; const float* gn1_b = (const float*)d_in[19];
    const float* gn2_w = (const float*)d_in[20]; const float* gn2_b = (const float*)d_in[21];
    const float* gn3_w = (const float*)d_in[22]; const float* gn3_b = (const float*)d_in[23];
    const float* gn4_w = (const float*)d_in[24]; const float* gn4_b = (const float*)d_in[25];

    float *c1, *c2, *c3, *w4, *t0, *t1, *big, *wsw;
    cudaGetSymbolAddress((void**)&c1,  g_c1);
    cudaGetSymbolAddress((void**)&c2,  g_c2);
    cudaGetSymbolAddress((void**)&c3,  g_c3);
    cudaGetSymbolAddress((void**)&w4,  g_w4);
    cudaGetSymbolAddress((void**)&t0,  g_t0);
    cudaGetSymbolAddress((void**)&t1,  g_t1);
    cudaGetSymbolAddress((void**)&big, g_big);
    cudaGetSymbolAddress((void**)&wsw, g_wsw);

    auto conv = [&](const float* in, const float* b, const float* skip, float* out,
                    int Cin, int Cout, int H, int W, bool lr) {
        dim3 g((H / 16) * (W / 16), (Cout + 31) / 32, NB);
        conv3x3_kernel<<<g, 256>>>(in, wsw, b, skip, out, Cin, Cout, H, W, lr ? 1 : 0);
    };

    // ---------------- encoder ----------------
    // w1 = wt(x): (16,12,128,128)
    wt_kernel<<<blocks_for((size_t)NB * 3 * 128 * 128), 256>>>(x, t0, 3, 256, 256);
    ws_kernel<<<16, 256>>>(conv1_w, wsw, 12 * 9);
    conv(t0, conv1_b, nullptr, c1, 12, 16, 128, 128, true);
    gn_kernel<<<NB * 2, 256>>>(c1, gn1_w, gn1_b, 16, 128 * 128, 2);

    // w2 = wt(c1): (16,64,64,64)
    wt_kernel<<<blocks_for((size_t)NB * 16 * 64 * 64), 256>>>(c1, t0, 16, 128, 128);
    ws_kernel<<<64, 256>>>(conv2_w, wsw, 64 * 9);
    conv(t0, conv2_b, nullptr, c2, 64, 64, 64, 64, true);
    gn_kernel<<<NB * 8, 256>>>(c2, gn2_w, gn2_b, 64, 64 * 64, 8);

    // w3 = wt(c2): (16,256,32,32)
    wt_kernel<<<blocks_for((size_t)NB * 64 * 32 * 32), 256>>>(c2, t0, 64, 64, 64);
    ws_kernel<<<256, 256>>>(conv3_w, wsw, 256 * 9);
    conv(t0, conv3_b, nullptr, c3, 256, 256, 32, 32, true);
    gn_kernel<<<NB * 32, 256>>>(c3, gn3_w, gn3_b, 256, 32 * 32, 32);

    // w4 = wt(c3): (16,1024,16,16)
    wt_kernel<<<blocks_for((size_t)NB * 256 * 16 * 16), 256>>>(c3, w4, 256, 32, 32);
    ws_kernel<<<1024, 256>>>(conv4_w, wsw, 1024 * 9);
    // c4
    conv(w4, conv4_b, nullptr, t0, 1024, 1024, 16, 16, true);
    gn_kernel<<<NB * 128, 256>>>(t0, gn4_w, gn4_b, 1024, 16 * 16, 128);
    // c5
    conv(t0, conv4_b, nullptr, t1, 1024, 1024, 16, 16, true);
    gn_kernel<<<NB * 128, 256>>>(t1, gn4_w, gn4_b, 1024, 16 * 16, 128);
    // ic4 = lrelu(c6 + w4)  (c6 = conv + bias, then skip add, then lrelu)
    conv(t1, conv4_b, w4, t0, 1024, 1024, 16, 16, true);

    // ---------------- decoder ----------------
    // iw4 = concat([c3, iwt(ic4)]) : (16,512,32,32)
    iwt_kernel<<<blocks_for((size_t)NB * 256 * 16 * 16), 256>>>(t0, big, 256, 16, 16, 256, 512);
    copy_ch_kernel<<<blocks_for((size_t)NB * 256 * 1024), 256>>>(c3, big, 256, 32 * 32, 512, 0);
    ws_kernel<<<256, 256>>>(convd4_w, wsw, 512 * 9);
    conv(big, convd4_b, nullptr, t1, 512, 256, 32, 32, true);
    gn_kernel<<<NB * 32, 256>>>(t1, gn3_w, gn3_b, 256, 32 * 32, 32);   // ic3

    // iw3 = concat([c2, iwt(ic3)]) : (16,128,64,64)
    iwt_kernel<<<blocks_for((size_t)NB * 64 * 32 * 32), 256>>>(t1, big, 64, 32, 32, 64, 128);
    copy_ch_kernel<<<blocks_for((size_t)NB * 64 * 4096), 256>>>(c2, big, 64, 64 * 64, 128, 0);
    ws_kernel<<<64, 256>>>(convd3_w, wsw, 128 * 9);
    conv(big, convd3_b, nullptr, t0, 128, 64, 64, 64, true);
    gn_kernel<<<NB * 8, 256>>>(t0, gn2_w, gn2_b, 64, 64 * 64, 8);      // ic2

    // iw2 = concat([c1, iwt(ic2)]) : (16,32,128,128)
    iwt_kernel<<<blocks_for((size_t)NB * 16 * 64 * 64), 256>>>(t0, big, 16, 64, 64, 16, 32);
    copy_ch_kernel<<<blocks_for((size_t)NB * 16 * 16384), 256>>>(c1, big, 16, 128 * 128, 32, 0);
    ws_kernel<<<16, 256>>>(convd2_w, wsw, 32 * 9);
    conv(big, convd2_b, nullptr, t1, 32, 16, 128, 128, true);
    gn_kernel<<<NB * 2, 256>>>(t1, gn1_w, gn1_b, 16, 128 * 128, 2);    // ic1

    // iw1 = lrelu(convd1(ic1)) : (16,12,128,128)
    ws_kernel<<<12, 256>>>(convd1_w, wsw, 16 * 9);
    conv(t1, convd1_b, nullptr, t0, 16, 12, 128, 128, true);

    // iwt(iw1): (16,3,256,256)
    iwt_kernel<<<blocks_for((size_t)NB * 3 * 128 * 128), 256>>>(t0, t1, 3, 128, 128, 0, 3);

    // y = ws_conv(., final_w (2,3,1,1), no bias)
    ws_kernel<<<2, 256>>>(final_w, wsw, 3);
    final_kernel<<<blocks_for((size_t)NB * 256 * 256), 256>>>(t1, wsw, (float*)d_out, 256 * 256);
}

// round 5
// speedup vs baseline: 6.3771x; 6.3771x over previous
#include <cuda_runtime.h>
#include <cuda_bf16.h>
#include <math.h>
#include <stdint.h>

#define NB 16
#define PADPIX 256
#define GEMM_HDR 1024
#define STAGE_BYTES 98304  // Ahi16K+Alo16K+Bhi32K+Blo32K
#define GEMM_SMEM (GEMM_HDR + 2 * STAGE_BYTES)

// tcgen05 is arch-SPECIFIC: only emit it on the sm_103a/f pass, not compute_103.
#if (defined(__CUDA_ARCH_SPECIFIC__) && (__CUDA_ARCH_SPECIFIC__ == 1030)) || \
    (defined(__CUDA_ARCH_FAMILY_SPECIFIC__) && (__CUDA_ARCH_FAMILY_SPECIFIC__ == 1030))
#define HAS_TCGEN05 1
#else
#define HAS_TCGEN05 0
#endif

__device__ float g_c1 [4194304];
__device__ float g_c2 [4194304];
__device__ float g_c3 [4194304];
__device__ float g_w4 [4194304];
__device__ float g_t0 [4194304];
__device__ float g_t1 [4194304];
__device__ float g_big[8388608];
__device__ float g_wsw[9437184];
__device__ __align__(1024) __nv_bfloat16 g_xhi[12582912];
__device__ __align__(1024) __nv_bfloat16 g_xlo[12582912];
__device__ __align__(1024) __nv_bfloat16 g_whi[9437184];
__device__ __align__(1024) __nv_bfloat16 g_wlo[9437184];

// ---------------- PTX helpers ----------------
__device__ __forceinline__ uint32_t smem_u32(const void* p) {
    uint32_t a;
    asm("{ .reg .u64 t; cvta.to.shared.u64 t, %1; cvt.u32.u64 %0, t; }" : "=r"(a) : "l"(p));
    return a;
}
__device__ __forceinline__ uint32_t elect_one() {
    uint32_t p;
    asm volatile("{\n\t.reg .pred p;\n\telect.sync _|p, 0xFFFFFFFF;\n\tselp.b32 %0, 1, 0, p;\n\t}" : "=r"(p));
    return p;
}
#define SWZ(off) ((off) ^ (((off) >> 3) & 0x70))
static constexpr uint64_t DESC_BASE =
    (uint64_t(2) << 61) | (uint64_t(1) << 46) | (uint64_t(64) << 32) | (uint64_t(1) << 16);
#define MK_DESC(a) (DESC_BASE | ((uint64_t)((a) >> 4) & 0x3FFF))

#define MBAR_INIT(a, c) asm volatile("mbarrier.init.shared.b64 [%0], %1;" :: "r"((uint32_t)(a)), "r"((uint32_t)(c)) : "memory")
#define MBAR_INVAL(a)   asm volatile("mbarrier.inval.shared.b64 [%0];" :: "r"((uint32_t)(a)) : "memory")
#define MBAR_WAIT(a, par) do { \
    uint32_t _m = (uint32_t)(a), _p = (uint32_t)(par), _d; \
    asm volatile("{\n\t.reg .pred p;\n\tmbarrier.try_wait.parity.acquire.cta.shared::cta.b64 p, [%1], %2;\n\tselp.b32 %0, 1, 0, p;\n\t}" \
        : "=r"(_d) : "r"(_m), "r"(_p) : "memory"); \
    if (!_d) { \
        asm volatile("{\n\t.reg .pred P1;\n\tWL_%=:\n\tmbarrier.try_wait.parity.acquire.cta.shared::cta.b64 P1, [%0], %1, 0x989680;\n\t@P1 bra.uni WD_%=;\n\tbra.uni WL_%=;\n\tWD_%=:\n\t}" \
            :: "r"(_m), "r"(_p) : "memory"); \
    } } while (0)

__device__ __forceinline__ void cp16(uint32_t dst, const void* src) {
    asm volatile("cp.async.cg.shared.global [%0], [%1], 16;" :: "r"(dst), "l"(src));
}

#if HAS_TCGEN05
#define TC_ALLOC(sa, n)  asm volatile("tcgen05.alloc.cta_group::1.sync.aligned.shared::cta.b32 [%0], %1;" :: "r"((uint32_t)(sa)), "r"((uint32_t)(n)) : "memory")
#define TC_DEALLOC(t, n) asm volatile("tcgen05.dealloc.cta_group::1.sync.aligned.b32 %0, %1;" :: "r"(t), "r"((uint32_t)(n)))
#define TC_COMMIT(mb)    asm volatile("tcgen05.commit.cta_group::1.mbarrier::arrive::one.shared::cluster.b64 [%0];" :: "r"((uint32_t)(mb)) : "memory")
#define TC_FENCE_AFTER()  asm volatile("tcgen05.fence::after_thread_sync;" ::: "memory")
#define TC_FENCE_BEFORE() asm volatile("tcgen05.fence::before_thread_sync;" ::: "memory")
#define TC_WAIT_LD()      asm volatile("tcgen05.wait::ld.sync.aligned;" ::: "memory")
#define FENCE_ASYNC()     asm volatile("fence.proxy.async.shared::cta;" ::: "memory")

#define TC_LD_X32(r, ta) \
    asm volatile("tcgen05.ld.sync.aligned.32x32b.x32.b32 " \
        "{%0,%1,%2,%3,%4,%5,%6,%7,%8,%9,%10,%11,%12,%13,%14,%15," \
        "%16,%17,%18,%19,%20,%21,%22,%23,%24,%25,%26,%27,%28,%29,%30,%31}, [%32];" \
        : "=r"((r)[0]),"=r"((r)[1]),"=r"((r)[2]),"=r"((r)[3]),"=r"((r)[4]),"=r"((r)[5]),"=r"((r)[6]),"=r"((r)[7]), \
          "=r"((r)[8]),"=r"((r)[9]),"=r"((r)[10]),"=r"((r)[11]),"=r"((r)[12]),"=r"((r)[13]),"=r"((r)[14]),"=r"((r)[15]), \
          "=r"((r)[16]),"=r"((r)[17]),"=r"((r)[18]),"=r"((r)[19]),"=r"((r)[20]),"=r"((r)[21]),"=r"((r)[22]),"=r"((r)[23]), \
          "=r"((r)[24]),"=r"((r)[25]),"=r"((r)[26]),"=r"((r)[27]),"=r"((r)[28]),"=r"((r)[29]),"=r"((r)[30]),"=r"((r)[31]) \
        : "r"(ta))

__device__ __forceinline__ void mma_ss(uint32_t d, uint64_t a, uint64_t b, uint32_t idesc, uint32_t acc) {
    asm volatile(
        "{\n\t.reg .pred p;\n\tsetp.ne.u32 p, %5, 0;\n\t"
        "tcgen05.mma.cta_group::1.kind::f16 [%0], %1, %2, %3, {%4, %4, %4, %4}, p;\n\t}"
        :: "r"(d), "l"(a), "l"(b), "r"(idesc), "r"(0u), "r"(acc) : "memory");
}
#define MMA_IDESC 0x8400490u  // f32 acc, bf16 x bf16, M=128, N=256
#endif // HAS_TCGEN05

// ---------------- pack ----------------
__global__ void pack_x_kernel(const float* __restrict__ src, __nv_bfloat16* __restrict__ hi,
                              __nv_bfloat16* __restrict__ lo, int C, int H, int W)
{
    int Wp = W + 2, HpWp = (H + 2) * Wp, HW = H * W;
    size_t total = (size_t)NB * H * W * C;
    for (size_t idx = (size_t)blockIdx.x * blockDim.x + threadIdx.x; idx < total;
         idx += (size_t)gridDim.x * blockDim.x) {
        int ci = (int)(idx % C); size_t t = idx / C;
        int x = (int)(t % W); t /= W;
        int y = (int)(t % H); int n = (int)(t / H);
        float v = src[((size_t)(n * C + ci)) * HW + y * W + x];
        __nv_bfloat16 h = __float2bfloat16(v);
        size_t row = (size_t)n * HpWp + (size_t)(y + 1) * Wp + (x + 1);
        hi[row * C + ci] = h;
        lo[row * C + ci] = __float2bfloat16(v - __bfloat162float(h));
    }
}
__global__ void pack_w_kernel(const float* __restrict__ w, __nv_bfloat16* __restrict__ hi,
                              __nv_bfloat16* __restrict__ lo, int Cout, int Cin)
{
    size_t total = (size_t)9 * Cout * Cin;
    for (size_t idx = (size_t)blockIdx.x * blockDim.x + threadIdx.x; idx < total;
         idx += (size_t)gridDim.x * blockDim.x) {
        int ci = (int)(idx % Cin); size_t t = idx / Cin;
        int co = (int)(t % Cout); int tap = (int)(t / Cout);
        float v = w[((size_t)co * Cin + ci) * 9 + tap];
        __nv_bfloat16 h = __float2bfloat16(v);
        hi[idx] = h;
        lo[idx] = __float2bfloat16(v - __bfloat162float(h));
    }
}

// ---------------- tcgen05 conv (implicit GEMM, 3-pass bf16 hi/lo) ----------------
__global__ void __launch_bounds__(128, 1) conv_mma_kernel(
    const __nv_bfloat16* __restrict__ Whi, const __nv_bfloat16* __restrict__ Wlo,
    const __nv_bfloat16* __restrict__ Xhi, const __nv_bfloat16* __restrict__ Xlo,
    const float* __restrict__ bias, const float* __restrict__ skip,
    float* __restrict__ out, int Cin, int Cout, int H, int W, int do_lrelu)
{
#if HAS_TCGEN05
    extern __shared__ char smem[];
    uint32_t sb = smem_u32(smem);
    int tid = threadIdx.x, wid = tid >> 5, lane = tid & 31;
    int Wp = W + 2, HpWp = (H + 2) * Wp;
    int Np = NB * HpWp;
    int px_base = blockIdx.x * 256;
    int co_base = blockIdx.y * 128;
    int kchunks = Cin >> 6;
    int n_chunks = 9 * kchunks;

    if (wid == 0) TC_ALLOC(sb + 0, 256);
    if (tid == 0) { MBAR_INIT(sb + 16, 1); MBAR_INIT(sb + 24, 1); }
    __syncthreads();
    uint32_t tmem;
    asm volatile("ld.shared.b32 %0, [%1];" : "=r"(tmem) : "r"(sb + 0));

    int r0 = tid >> 3, g = tid & 7;

    auto load_chunk = [&](int i) {
        uint32_t stage = sb + GEMM_HDR + (i & 1) * STAGE_BYTES;
        int tap = i / kchunks, kc = i - tap * kchunks;
        int shift = (tap / 3 - 1) * Wp + (tap % 3 - 1);
        const __nv_bfloat16* ah = Whi + (size_t)(tap * Cout + co_base) * Cin + kc * 64;
        const __nv_bfloat16* al = Wlo + (size_t)(tap * Cout + co_base) * Cin + kc * 64;
        const __nv_bfloat16* bh = Xhi + (size_t)(px_base + shift) * Cin + kc * 64;
        const __nv_bfloat16* bl = Xlo + (size_t)(px_base + shift) * Cin + kc * 64;
#pragma unroll
        for (int j = 0; j < 8; j++) {
            int row = r0 + 16 * j;
            uint32_t d = SWZ((uint32_t)(row * 128 + g * 16));
            cp16(stage + 0     + d, ah + (size_t)row * Cin + g * 8);
            cp16(stage + 16384 + d, al + (size_t)row * Cin + g * 8);
        }
#pragma unroll
        for (int j = 0; j < 16; j++) {
            int row = r0 + 16 * j;
            uint32_t d = SWZ((uint32_t)(row * 128 + g * 16));
            cp16(stage + 32768 + d, bh + (size_t)row * Cin + g * 8);
            cp16(stage + 65536 + d, bl + (size_t)row * Cin + g * 8);
        }
        asm volatile("cp.async.commit_group;" ::: "memory");
    };

    load_chunk(0);
    for (int i = 0; i < n_chunks; i++) {
        if (i + 1 < n_chunks) {
            if (i >= 1) MBAR_WAIT(sb + 16 + 8 * ((i + 1) & 1), ((i - 1) >> 1) & 1);
            load_chunk(i + 1);
            asm volatile("cp.async.wait_group 1;" ::: "memory");
        } else {
            asm volatile("cp.async.wait_group 0;" ::: "memory");
        }
        __syncthreads();
        if (wid == 0 && elect_one()) {
            FENCE_ASYNC();
            uint32_t stage = sb + GEMM_HDR + (i & 1) * STAGE_BYTES;
            uint64_t dAh = MK_DESC(stage), dAl = MK_DESC(stage + 16384);
            uint64_t dBh = MK_DESC(stage + 32768), dBl = MK_DESC(stage + 65536);
#pragma unroll
            for (int k = 0; k < 4; k++)
                mma_ss(tmem, dAh + 2 * k, dBh + 2 * k, MMA_IDESC, (i != 0 || k != 0) ? 1u : 0u);
#pragma unroll
            for (int k = 0; k < 4; k++)
                mma_ss(tmem, dAl + 2 * k, dBh + 2 * k, MMA_IDESC, 1u);
#pragma unroll
            for (int k = 0; k < 4; k++)
                mma_ss(tmem, dAh + 2 * k, dBl + 2 * k, MMA_IDESC, 1u);
            TC_COMMIT(sb + 16 + 8 * (i & 1));
        }
    }
    {
        int uses0 = (n_chunks + 1) >> 1, uses1 = n_chunks >> 1;
        MBAR_WAIT(sb + 16, (uses0 - 1) & 1);
        if (uses1 > 0) MBAR_WAIT(sb + 24, (uses1 - 1) & 1);
    }
    TC_FENCE_AFTER();

    int co = co_base + wid * 32 + lane;
    float bv = (co < Cout) ? bias[co] : 0.f;
    for (int cb = 0; cb < 256; cb += 32) {
        uint32_t regs[32];
        TC_LD_X32(regs, tmem + cb);
        TC_WAIT_LD();
        if (co < Cout) {
#pragma unroll
            for (int c = 0; c < 32; c++) {
                int p = px_base + cb + c;
                if (p >= Np) continue;
                int n = p / HpWp; int rem = p - n * HpWp;
                int yp = rem / Wp; int xp = rem - yp * Wp;
                if ((unsigned)(yp - 1) < (unsigned)H && (unsigned)(xp - 1) < (unsigned)W) {
                    size_t o = (((size_t)n * Cout + co) * H + (yp - 1)) * W + (xp - 1);
                    float v = __uint_as_float(regs[c]) + bv;
                    if (skip) v += skip[o];
                    if (do_lrelu) v = v > 0.f ? v : 0.2f * v;
                    out[o] = v;
                }
            }
        }
    }
    TC_FENCE_BEFORE();
    __syncthreads();
    if (tid == 0) { MBAR_INVAL(sb + 16); MBAR_INVAL(sb + 24); }
    __syncthreads();
    if (wid == 0) TC_DEALLOC(tmem, 256);
#endif // HAS_TCGEN05
}

// ---------------- fp32 helper kernels ----------------
__global__ void ws_kernel(const float* __restrict__ w, float* __restrict__ out, int K)
{
    int f = blockIdx.x;
    const float* wf = w + (size_t)f * K;
    __shared__ float red[256];
    float s = 0.f;
    for (int i = threadIdx.x; i < K; i += 256) s += wf[i];
    red[threadIdx.x] = s; __syncthreads();
    for (int o = 128; o; o >>= 1) { if (threadIdx.x < o) red[threadIdx.x] += red[threadIdx.x + o]; __syncthreads(); }
    float mean = red[0] / (float)K;
    __syncthreads();
    float ss = 0.f;
    for (int i = threadIdx.x; i < K; i += 256) { float d = wf[i] - mean; ss += d * d; }
    red[threadIdx.x] = ss; __syncthreads();
    for (int o = 128; o; o >>= 1) { if (threadIdx.x < o) red[threadIdx.x] += red[threadIdx.x + o]; __syncthreads(); }
    float inv = 1.0f / (sqrtf(red[0] / (float)(K - 1)) + 1e-5f);
    for (int i = threadIdx.x; i < K; i += 256)
        out[(size_t)f * K + i] = (wf[i] - mean) * inv;
}

__global__ void gn_kernel(float* __restrict__ x, const float* __restrict__ gamma,
                          const float* __restrict__ beta, int C, int HW, int G)
{
    int n = blockIdx.x / G, grp = blockIdx.x % G;
    int cpg = C / G;
    int len = cpg * HW;
    size_t base = ((size_t)n * C + (size_t)grp * cpg) * HW;
    __shared__ float r1[1024], r2[1024];
    float s = 0.f, ss = 0.f;
    for (int i = threadIdx.x; i < len; i += 1024) { float v = x[base + i]; s += v; ss += v * v; }
    r1[threadIdx.x] = s; r2[threadIdx.x] = ss; __syncthreads();
    for (int o = 512; o; o >>= 1) {
        if (threadIdx.x < o) { r1[threadIdx.x] += r1[threadIdx.x + o]; r2[threadIdx.x] += r2[threadIdx.x + o]; }
        __syncthreads();
    }
    float mean = r1[0] / (float)len;
    float var  = r2[0] / (float)len - mean * mean;
    float inv  = rsqrtf(var + 1e-5f);
    for (int i = threadIdx.x; i < len; i += 1024) {
        int c = grp * cpg + i / HW;
        x[base + i] = (x[base + i] - mean) * inv * gamma[c] + beta[c];
    }
}

__global__ void wt_kernel(const float* __restrict__ in, float* __restrict__ out, int C, int H, int W)
{
    int h2 = H >> 1, w2 = W >> 1;
    size_t total = (size_t)NB * C * h2 * w2;
    for (size_t idx = (size_t)blockIdx.x * blockDim.x + threadIdx.x; idx < total;
         idx += (size_t)gridDim.x * blockDim.x) {
        int j = (int)(idx % w2); size_t t = idx / w2;
        int i = (int)(t % h2); t /= h2;
        int c = (int)(t % C); int n = (int)(t / C);
        const float* p = in + ((size_t)(n * C + c) * H + 2 * i) * W + 2 * j;
        float a = p[0], b = p[1], cc = p[W], d = p[W + 1];
        size_t cs = (size_t)h2 * w2;
        size_t ob = (((size_t)n * 4 * C + 4 * c) * h2 + i) * w2 + j;
        out[ob]          = 0.25f * (a + b + cc + d);
        out[ob + cs]     = 0.25f * (a + b - cc - d) + 0.5f;
        out[ob + 2 * cs] = 0.25f * (a - b + cc - d) + 0.5f;
        out[ob + 3 * cs] = 0.25f * (a - b - cc + d) + 0.5f;
    }
}

__global__ void iwt_kernel(const float* __restrict__ in, float* __restrict__ out,
                           int C, int h, int w, int c_off, int Cdst)
{
    size_t total = (size_t)NB * C * h * w;
    for (size_t idx = (size_t)blockIdx.x * blockDim.x + threadIdx.x; idx < total;
         idx += (size_t)gridDim.x * blockDim.x) {
        int j = (int)(idx % w); size_t t = idx / w;
        int i = (int)(t % h); t /= h;
        int c = (int)(t % C); int n = (int)(t / C);
        size_t cs = (size_t)h * w;
        size_t ib = (((size_t)n * 4 * C + 4 * c) * h + i) * w + j;
        float s0 = in[ib];
        float s1 = 2.f * in[ib + cs]     - 1.f;
        float s2 = 2.f * in[ib + 2 * cs] - 1.f;
        float s3 = 2.f * in[ib + 3 * cs] - 1.f;
        float* q = out + (((size_t)n * Cdst + c_off + c) * 2 * h + 2 * i) * 2 * w + 2 * j;
        q[0]         = s0 + 0.5f * ( s1 + s2 + s3);
        q[1]         = s0 + 0.5f * ( s1 - s2 - s3);
        q[2 * w]     = s0 + 0.5f * (-s1 + s2 - s3);
        q[2 * w + 1] = s0 + 0.5f * (-s1 - s2 + s3);
    }
}

__global__ void copy_ch_kernel(const float* __restrict__ src, float* __restrict__ dst,
                               int C, int HW, int Cdst, int c_off)
{
    size_t total = (size_t)NB * C * HW;
    for (size_t idx = (size_t)blockIdx.x * blockDim.x + threadIdx.x; idx < total;
         idx += (size_t)gridDim.x * blockDim.x) {
        int p = (int)(idx % HW); size_t t = idx / HW;
        int c = (int)(t % C); int n = (int)(t / C);
        dst[((size_t)n * Cdst + c_off + c) * HW + p] = src[idx];
    }
}

__global__ __launch_bounds__(256) void conv3x3_kernel(
    const float* __restrict__ in, const float* __restrict__ wgt,
    const float* __restrict__ bias, const float* __restrict__ skip,
    float* __restrict__ out, int Cin, int Cout, int H, int W, int do_lrelu)
{
    __shared__ __align__(16) float s_in[4][18][18];
    __shared__ __align__(16) float s_w[4][9][32];
    int tiles_x = W >> 4;
    int tx0 = (blockIdx.x % tiles_x) << 4;
    int ty0 = (blockIdx.x / tiles_x) << 4;
    int co_base = blockIdx.y << 5;
    int n = blockIdx.z;
    int tx = threadIdx.x;
    int cog8 = (tx >> 6) << 3;
    int pid  = tx & 63;
    int prow = pid >> 2;
    int pcol = (pid & 3) << 2;

    float acc[8][4];
#pragma unroll
    for (int r = 0; r < 8; r++)
#pragma unroll
        for (int p = 0; p < 4; p++) acc[r][p] = 0.f;

    for (int cc = 0; cc < Cin; cc += 4) {
        for (int idx = tx; idx < 4 * 9 * 32; idx += 256) {
            int co = idx & 31;
            int tap = (idx >> 5) % 9;
            int ci = (idx >> 5) / 9;
            float v = 0.f;
            if (co_base + co < Cout && cc + ci < Cin)
                v = wgt[((size_t)(co_base + co) * Cin + cc + ci) * 9 + tap];
            s_w[ci][tap][co] = v;
        }
        for (int idx = tx; idx < 4 * 18 * 18; idx += 256) {
            int ix = idx % 18; int t = idx / 18;
            int iy = t % 18;  int ci = t / 18;
            int gy = ty0 + iy - 1, gx = tx0 + ix - 1;
            float v = 0.f;
            if (cc + ci < Cin && gy >= 0 && gy < H && gx >= 0 && gx < W)
                v = in[((size_t)(n * Cin + cc + ci) * H + gy) * W + gx];
            s_in[ci][iy][ix] = v;
        }
        __syncthreads();
#pragma unroll
        for (int ci = 0; ci < 4; ci++)
#pragma unroll
            for (int dy = 0; dy < 3; dy++)
#pragma unroll
                for (int dx = 0; dx < 3; dx++) {
                    float xv[4];
#pragma unroll
                    for (int p = 0; p < 4; p++) xv[p] = s_in[ci][prow + dy][pcol + dx + p];
                    const float* wp = &s_w[ci][dy * 3 + dx][cog8];
                    float4 wa = *reinterpret_cast<const float4*>(wp);
                    float4 wb = *reinterpret_cast<const float4*>(wp + 4);
                    float wv[8] = {wa.x, wa.y, wa.z, wa.w, wb.x, wb.y, wb.z, wb.w};
#pragma unroll
                    for (int r = 0; r < 8; r++)
#pragma unroll
                        for (int p = 0; p < 4; p++) acc[r][p] = fmaf(wv[r], xv[p], acc[r][p]);
                }
        __syncthreads();
    }
    int oy = ty0 + prow;
#pragma unroll
    for (int r = 0; r < 8; r++) {
        int co = co_base + cog8 + r;
        if (co < Cout) {
            float b = bias ? bias[co] : 0.f;
            size_t ob = ((size_t)(n * Cout + co) * H + oy) * W + tx0 + pcol;
#pragma unroll
            for (int p = 0; p < 4; p++) {
                float v = acc[r][p] + b;
                if (skip) v += skip[ob + p];
                if (do_lrelu) v = v > 0.f ? v : 0.2f * v;
                out[ob + p] = v;
            }
        }
    }
}

__global__ void final_kernel(const float* __restrict__ in, const float* __restrict__ w,
                             float* __restrict__ out, int HW)
{
    size_t total = (size_t)NB * HW;
    for (size_t idx = (size_t)blockIdx.x * blockDim.x + threadIdx.x; idx < total;
         idx += (size_t)gridDim.x * blockDim.x) {
        int p = (int)(idx % HW); int n = (int)(idx / HW);
        const float* ip = in + (size_t)n * 3 * HW + p;
        float x0 = ip[0], x1 = ip[HW], x2 = ip[2 * HW];
        float* op = out + (size_t)n * 2 * HW + p;
        op[0]  = w[0] * x0 + w[1] * x1 + w[2] * x2;
        op[HW] = w[3] * x0 + w[4] * x1 + w[5] * x2;
    }
}

// ---------------- host ----------------
static inline int blocks_for(size_t n) { return (int)((n + 255) / 256); }

extern "C" void kernel_launch(void* const* d_in, const int* in_sizes, int n_in,
                              void* d_out, int out_size)
{
    const float* x        = (const float*)d_in[0];
    const float* conv1_w  = (const float*)d_in[1];  const float* conv1_b  = (const float*)d_in[2];
    const float* conv2_w  = (const float*)d_in[3];  const float* conv2_b  = (const float*)d_in[4];
    const float* conv3_w  = (const float*)d_in[5];  const float* conv3_b  = (const float*)d_in[6];
    const float* conv4_w  = (const float*)d_in[7];  const float* conv4_b  = (const float*)d_in[8];
    const float* convd1_w = (const float*)d_in[9];  const float* convd1_b = (const float*)d_in[10];
    const float* convd2_w = (const float*)d_in[11]; const float* convd2_b = (const float*)d_in[12];
    const float* convd3_w = (const float*)d_in[13]; const float* convd3_b = (const float*)d_in[14];
    const float* convd4_w = (const float*)d_in[15]; const float* convd4_b = (const float*)d_in[16];
    const float* final_w  = (const float*)d_in[17];
    const float* gn1_w = (const float*)d_in[18]; const float* gn1_b = (const float*)d_in[19];
    const float* gn2_w = (const float*)d_in[20]; const float* gn2_b = (const float*)d_in[21];
    const float* gn3_w = (const float*)d_in[22]; const float* gn3_b = (const float*)d_in[23];
    const float* gn4_w = (const float*)d_in[24]; const float* gn4_b = (const float*)d_in[25];

    float *c1, *c2, *c3, *w4, *t0, *t1, *big, *wsw;
    __nv_bfloat16 *xhi, *xlo, *whi, *wlo;
    cudaGetSymbolAddress((void**)&c1,  g_c1);
    cudaGetSymbolAddress((void**)&c2,  g_c2);
    cudaGetSymbolAddress((void**)&c3,  g_c3);
    cudaGetSymbolAddress((void**)&w4,  g_w4);
    cudaGetSymbolAddress((void**)&t0,  g_t0);
    cudaGetSymbolAddress((void**)&t1,  g_t1);
    cudaGetSymbolAddress((void**)&big, g_big);
    cudaGetSymbolAddress((void**)&wsw, g_wsw);
    cudaGetSymbolAddress((void**)&xhi, g_xhi);
    cudaGetSymbolAddress((void**)&xlo, g_xlo);
    cudaGetSymbolAddress((void**)&whi, g_whi);
    cudaGetSymbolAddress((void**)&wlo, g_wlo);

    cudaFuncSetAttribute(conv_mma_kernel, cudaFuncAttributeMaxDynamicSharedMemorySize, GEMM_SMEM);

    auto conv_f32 = [&](const float* in, const float* b, const float* skip, float* out,
                        int Cin, int Cout, int H, int W) {
        dim3 g((H / 16) * (W / 16), (Cout + 31) / 32, NB);
        conv3x3_kernel<<<g, 256>>>(in, wsw, b, skip, out, Cin, Cout, H, W, 1);
    };
    auto conv_mma = [&](const float* src, const float* w, const float* b, const float* skip,
                        float* out, int Cin, int Cout, int H, int W) {
        ws_kernel<<<Cout, 256>>>(w, wsw, Cin * 9);
        pack_w_kernel<<<blocks_for((size_t)9 * Cout * Cin), 256>>>(wsw, whi, wlo, Cout, Cin);
        int Wp = W + 2, Np = NB * (H + 2) * Wp;
        int Ntiles = (Np + 255) / 256, Mtiles = (Cout + 127) / 128;
        size_t xbytes = (size_t)(2 * PADPIX + Ntiles * 256) * Cin * sizeof(__nv_bfloat16);
        cudaMemsetAsync(xhi, 0, xbytes);
        cudaMemsetAsync(xlo, 0, xbytes);
        pack_x_kernel<<<blocks_for((size_t)NB * H * W * Cin), 256>>>(
            src, xhi + (size_t)PADPIX * Cin, xlo + (size_t)PADPIX * Cin, Cin, H, W);
        dim3 g(Ntiles, Mtiles);
        conv_mma_kernel<<<g, 128, GEMM_SMEM>>>(whi, wlo, xhi + (size_t)PADPIX * Cin,
                                               xlo + (size_t)PADPIX * Cin, b, skip, out,
                                               Cin, Cout, H, W, 1);
    };

    // encoder
    wt_kernel<<<blocks_for((size_t)NB * 3 * 128 * 128), 256>>>(x, t0, 3, 256, 256);
    ws_kernel<<<16, 256>>>(conv1_w, wsw, 12 * 9);
    conv_f32(t0, conv1_b, nullptr, c1, 12, 16, 128, 128);
    gn_kernel<<<NB * 2, 1024>>>(c1, gn1_w, gn1_b, 16, 128 * 128, 2);

    wt_kernel<<<blocks_for((size_t)NB * 16 * 64 * 64), 256>>>(c1, t0, 16, 128, 128);
    conv_mma(t0, conv2_w, conv2_b, nullptr, c2, 64, 64, 64, 64);
    gn_kernel<<<NB * 8, 1024>>>(c2, gn2_w, gn2_b, 64, 64 * 64, 8);

    wt_kernel<<<blocks_for((size_t)NB * 64 * 32 * 32), 256>>>(c2, t0, 64, 64, 64);
    conv_mma(t0, conv3_w, conv3_b, nullptr, c3, 256, 256, 32, 32);
    gn_kernel<<<NB * 32, 1024>>>(c3, gn3_w, gn3_b, 256, 32 * 32, 32);

    wt_kernel<<<blocks_for((size_t)NB * 256 * 16 * 16), 256>>>(c3, w4, 256, 32, 32);
    conv_mma(w4, conv4_w, conv4_b, nullptr, t0, 1024, 1024, 16, 16);
    gn_kernel<<<NB * 128, 1024>>>(t0, gn4_w, gn4_b, 1024, 16 * 16, 128);
    conv_mma(t0, conv4_w, conv4_b, nullptr, t1, 1024, 1024, 16, 16);
    gn_kernel<<<NB * 128, 1024>>>(t1, gn4_w, gn4_b, 1024, 16 * 16, 128);
    conv_mma(t1, conv4_w, conv4_b, w4, t0, 1024, 1024, 16, 16);  // ic4

    // decoder
    iwt_kernel<<<blocks_for((size_t)NB * 256 * 16 * 16), 256>>>(t0, big, 256, 16, 16, 256, 512);
    copy_ch_kernel<<<blocks_for((size_t)NB * 256 * 1024), 256>>>(c3, big, 256, 32 * 32, 512, 0);
    conv_mma(big, convd4_w, convd4_b, nullptr, t1, 512, 256, 32, 32);
    gn_kernel<<<NB * 32, 1024>>>(t1, gn3_w, gn3_b, 256, 32 * 32, 32);  // ic3

    iwt_kernel<<<blocks_for((size_t)NB * 64 * 32 * 32), 256>>>(t1, big, 64, 32, 32, 64, 128);
    copy_ch_kernel<<<blocks_for((size_t)NB * 64 * 4096), 256>>>(c2, big, 64, 64 * 64, 128, 0);
    conv_mma(big, convd3_w, convd3_b, nullptr, t0, 128, 64, 64, 64);
    gn_kernel<<<NB * 8, 1024>>>(t0, gn2_w, gn2_b, 64, 64 * 64, 8);     // ic2

    iwt_kernel<<<blocks_for((size_t)NB * 16 * 64 * 64), 256>>>(t0, big, 16, 64, 64, 16, 32);
    copy_ch_kernel<<<blocks_for((size_t)NB * 16 * 16384), 256>>>(c1, big, 16, 128 * 128, 32, 0);
    ws_kernel<<<16, 256>>>(convd2_w, wsw, 32 * 9);
    conv_f32(big, convd2_b, nullptr, t1, 32, 16, 128, 128);
    gn_kernel<<<NB * 2, 1024>>>(t1, gn1_w, gn1_b, 16, 128 * 128, 2);   // ic1

    ws_kernel<<<12, 256>>>(convd1_w, wsw, 16 * 9);
    conv_f32(t1, convd1_b, nullptr, t0, 16, 12, 128, 128);

    iwt_kernel<<<blocks_for((size_t)NB * 3 * 128 * 128), 256>>>(t0, t1, 3, 128, 128, 0, 3);
    ws_kernel<<<2, 256>>>(final_w, wsw, 3);
    final_kernel<<<blocks_for((size_t)NB * 256 * 256), 256>>>(t1, wsw, (float*)d_out, 256 * 256);
}

// round 6
// speedup vs baseline: 7.0341x; 1.1030x over previous
#include <cuda_runtime.h>
#include <cuda_bf16.h>
#include <math.h>
#include <stdint.h>

#define NB 16
#define PADPIX 256
#define GEMM_HDR 1024
#define STAGE_BYTES 98304  // Ahi16K+Alo16K+Bhi32K+Blo32K
#define GEMM_SMEM (GEMM_HDR + 2 * STAGE_BYTES)

// tcgen05 is arch-SPECIFIC: only emit it on the sm_103a/f pass, not compute_103.
#if (defined(__CUDA_ARCH_SPECIFIC__) && (__CUDA_ARCH_SPECIFIC__ == 1030)) || \
    (defined(__CUDA_ARCH_FAMILY_SPECIFIC__) && (__CUDA_ARCH_FAMILY_SPECIFIC__ == 1030))
#define HAS_TCGEN05 1
#else
#define HAS_TCGEN05 0
#endif

__device__ float g_c1 [4194304];
__device__ float g_c2 [4194304];
__device__ float g_c3 [4194304];
__device__ float g_w4 [4194304];
__device__ float g_t0 [4194304];
__device__ float g_t1 [4194304];
__device__ float g_big[8388608];
__device__ float g_wsw[9437184];
__device__ float g_part[16384];
__device__ float g_mstats[4096];
__device__ __align__(1024) __nv_bfloat16 g_xhi[12582912];
__device__ __align__(1024) __nv_bfloat16 g_xlo[12582912];
__device__ __align__(1024) __nv_bfloat16 g_whi[9437184];
__device__ __align__(1024) __nv_bfloat16 g_wlo[9437184];

// ---------------- PTX helpers ----------------
__device__ __forceinline__ uint32_t smem_u32(const void* p) {
    uint32_t a;
    asm("{ .reg .u64 t; cvta.to.shared.u64 t, %1; cvt.u32.u64 %0, t; }" : "=r"(a) : "l"(p));
    return a;
}
__device__ __forceinline__ uint32_t elect_one() {
    uint32_t p;
    asm volatile("{\n\t.reg .pred p;\n\telect.sync _|p, 0xFFFFFFFF;\n\tselp.b32 %0, 1, 0, p;\n\t}" : "=r"(p));
    return p;
}
#define SWZ(off) ((off) ^ (((off) >> 3) & 0x70))
static constexpr uint64_t DESC_BASE =
    (uint64_t(2) << 61) | (uint64_t(1) << 46) | (uint64_t(64) << 32) | (uint64_t(1) << 16);
#define MK_DESC(a) (DESC_BASE | ((uint64_t)((a) >> 4) & 0x3FFF))

#define MBAR_INIT(a, c) asm volatile("mbarrier.init.shared.b64 [%0], %1;" :: "r"((uint32_t)(a)), "r"((uint32_t)(c)) : "memory")
#define MBAR_INVAL(a)   asm volatile("mbarrier.inval.shared.b64 [%0];" :: "r"((uint32_t)(a)) : "memory")
#define MBAR_WAIT(a, par) do { \
    uint32_t _m = (uint32_t)(a), _p = (uint32_t)(par), _d; \
    asm volatile("{\n\t.reg .pred p;\n\tmbarrier.try_wait.parity.acquire.cta.shared::cta.b64 p, [%1], %2;\n\tselp.b32 %0, 1, 0, p;\n\t}" \
        : "=r"(_d) : "r"(_m), "r"(_p) : "memory"); \
    if (!_d) { \
        asm volatile("{\n\t.reg .pred P1;\n\tWL_%=:\n\tmbarrier.try_wait.parity.acquire.cta.shared::cta.b64 P1, [%0], %1, 0x989680;\n\t@P1 bra.uni WD_%=;\n\tbra.uni WL_%=;\n\tWD_%=:\n\t}" \
            :: "r"(_m), "r"(_p) : "memory"); \
    } } while (0)

__device__ __forceinline__ void cp16(uint32_t dst, const void* src) {
    asm volatile("cp.async.cg.shared.global [%0], [%1], 16;" :: "r"(dst), "l"(src));
}

#if HAS_TCGEN05
#define TC_ALLOC(sa, n)  asm volatile("tcgen05.alloc.cta_group::1.sync.aligned.shared::cta.b32 [%0], %1;" :: "r"((uint32_t)(sa)), "r"((uint32_t)(n)) : "memory")
#define TC_DEALLOC(t, n) asm volatile("tcgen05.dealloc.cta_group::1.sync.aligned.b32 %0, %1;" :: "r"(t), "r"((uint32_t)(n)))
#define TC_COMMIT(mb)    asm volatile("tcgen05.commit.cta_group::1.mbarrier::arrive::one.shared::cluster.b64 [%0];" :: "r"((uint32_t)(mb)) : "memory")
#define TC_FENCE_AFTER()  asm volatile("tcgen05.fence::after_thread_sync;" ::: "memory")
#define TC_FENCE_BEFORE() asm volatile("tcgen05.fence::before_thread_sync;" ::: "memory")
#define TC_WAIT_LD()      asm volatile("tcgen05.wait::ld.sync.aligned;" ::: "memory")
#define FENCE_ASYNC()     asm volatile("fence.proxy.async.shared::cta;" ::: "memory")

#define TC_LD_X32(r, ta) \
    asm volatile("tcgen05.ld.sync.aligned.32x32b.x32.b32 " \
        "{%0,%1,%2,%3,%4,%5,%6,%7,%8,%9,%10,%11,%12,%13,%14,%15," \
        "%16,%17,%18,%19,%20,%21,%22,%23,%24,%25,%26,%27,%28,%29,%30,%31}, [%32];" \
        : "=r"((r)[0]),"=r"((r)[1]),"=r"((r)[2]),"=r"((r)[3]),"=r"((r)[4]),"=r"((r)[5]),"=r"((r)[6]),"=r"((r)[7]), \
          "=r"((r)[8]),"=r"((r)[9]),"=r"((r)[10]),"=r"((r)[11]),"=r"((r)[12]),"=r"((r)[13]),"=r"((r)[14]),"=r"((r)[15]), \
          "=r"((r)[16]),"=r"((r)[17]),"=r"((r)[18]),"=r"((r)[19]),"=r"((r)[20]),"=r"((r)[21]),"=r"((r)[22]),"=r"((r)[23]), \
          "=r"((r)[24]),"=r"((r)[25]),"=r"((r)[26]),"=r"((r)[27]),"=r"((r)[28]),"=r"((r)[29]),"=r"((r)[30]),"=r"((r)[31]) \
        : "r"(ta))

__device__ __forceinline__ void mma_ss(uint32_t d, uint64_t a, uint64_t b, uint32_t idesc, uint32_t acc) {
    asm volatile(
        "{\n\t.reg .pred p;\n\tsetp.ne.u32 p, %5, 0;\n\t"
        "tcgen05.mma.cta_group::1.kind::f16 [%0], %1, %2, %3, {%4, %4, %4, %4}, p;\n\t}"
        :: "r"(d), "l"(a), "l"(b), "r"(idesc), "r"(0u), "r"(acc) : "memory");
}
#define MMA_IDESC 0x8400490u  // f32 acc, bf16 x bf16, M=128, N=256
#endif // HAS_TCGEN05

// ---------------- pack ----------------
__global__ void pack_x_kernel(const float* __restrict__ src, __nv_bfloat16* __restrict__ hi,
                              __nv_bfloat16* __restrict__ lo, int C, int H, int W)
{
    int Wp = W + 2, HpWp = (H + 2) * Wp, HW = H * W;
    size_t total = (size_t)NB * H * W * C;
    for (size_t idx = (size_t)blockIdx.x * blockDim.x + threadIdx.x; idx < total;
         idx += (size_t)gridDim.x * blockDim.x) {
        int ci = (int)(idx % C); size_t t = idx / C;
        int x = (int)(t % W); t /= W;
        int y = (int)(t % H); int n = (int)(t / H);
        float v = src[((size_t)(n * C + ci)) * HW + y * W + x];
        __nv_bfloat16 h = __float2bfloat16(v);
        size_t row = (size_t)n * HpWp + (size_t)(y + 1) * Wp + (x + 1);
        hi[row * C + ci] = h;
        lo[row * C + ci] = __float2bfloat16(v - __bfloat162float(h));
    }
}
__global__ void pack_w_kernel(const float* __restrict__ w, __nv_bfloat16* __restrict__ hi,
                              __nv_bfloat16* __restrict__ lo, int Cout, int Cin)
{
    size_t total = (size_t)9 * Cout * Cin;
    for (size_t idx = (size_t)blockIdx.x * blockDim.x + threadIdx.x; idx < total;
         idx += (size_t)gridDim.x * blockDim.x) {
        int ci = (int)(idx % Cin); size_t t = idx / Cin;
        int co = (int)(t % Cout); int tap = (int)(t / Cout);
        float v = w[((size_t)co * Cin + ci) * 9 + tap];
        __nv_bfloat16 h = __float2bfloat16(v);
        hi[idx] = h;
        lo[idx] = __float2bfloat16(v - __bfloat162float(h));
    }
}

// Fused Haar forward + bf16 hi/lo pack (optionally also writes fp32 NCHW out).
// in: (NB,C,H,W). Packed out: channel 4c+k at padded pixel (i+1,j+1), Cdst=4C.
__global__ void wt_pack_kernel(const float* __restrict__ in, float* __restrict__ outf,
                               __nv_bfloat16* __restrict__ hi, __nv_bfloat16* __restrict__ lo,
                               int C, int H, int W)
{
    int h2 = H >> 1, w2 = W >> 1;
    int C4 = 4 * C;
    int Wp = w2 + 2, HpWp = (h2 + 2) * Wp;
    size_t total = (size_t)NB * C * h2 * w2;
    for (size_t idx = (size_t)blockIdx.x * blockDim.x + threadIdx.x; idx < total;
         idx += (size_t)gridDim.x * blockDim.x) {
        int j = (int)(idx % w2); size_t t = idx / w2;
        int i = (int)(t % h2); t /= h2;
        int c = (int)(t % C); int n = (int)(t / C);
        const float* p = in + ((size_t)(n * C + c) * H + 2 * i) * W + 2 * j;
        float a = p[0], b = p[1], cc = p[W], d = p[W + 1];
        float v0 = 0.25f * (a + b + cc + d);
        float v1 = 0.25f * (a + b - cc - d) + 0.5f;
        float v2 = 0.25f * (a - b + cc - d) + 0.5f;
        float v3 = 0.25f * (a - b - cc + d) + 0.5f;
        if (outf) {
            size_t cs = (size_t)h2 * w2;
            size_t ob = (((size_t)n * C4 + 4 * c) * h2 + i) * w2 + j;
            outf[ob] = v0; outf[ob + cs] = v1; outf[ob + 2 * cs] = v2; outf[ob + 3 * cs] = v3;
        }
        size_t row = (size_t)n * HpWp + (size_t)(i + 1) * Wp + (j + 1);
        size_t base = row * C4 + 4 * c;
        float vs[4] = {v0, v1, v2, v3};
#pragma unroll
        for (int k = 0; k < 4; k++) {
            __nv_bfloat16 h = __float2bfloat16(vs[k]);
            hi[base + k] = h;
            lo[base + k] = __float2bfloat16(vs[k] - __bfloat162float(h));
        }
    }
}

// ---------------- tcgen05 conv (implicit GEMM, 3-pass bf16 hi/lo) ----------------
__global__ void __launch_bounds__(128, 1) conv_mma_kernel(
    const __nv_bfloat16* __restrict__ Whi, const __nv_bfloat16* __restrict__ Wlo,
    const __nv_bfloat16* __restrict__ Xhi, const __nv_bfloat16* __restrict__ Xlo,
    const float* __restrict__ bias, const float* __restrict__ skip,
    float* __restrict__ out, int Cin, int Cout, int H, int W, int do_lrelu)
{
#if HAS_TCGEN05
    extern __shared__ char smem[];
    uint32_t sb = smem_u32(smem);
    int tid = threadIdx.x, wid = tid >> 5, lane = tid & 31;
    int Wp = W + 2, HpWp = (H + 2) * Wp;
    int Np = NB * HpWp;
    int px_base = blockIdx.x * 256;
    int co_base = blockIdx.y * 128;
    int kchunks = Cin >> 6;
    int n_chunks = 9 * kchunks;

    if (wid == 0) TC_ALLOC(sb + 0, 256);
    if (tid == 0) { MBAR_INIT(sb + 16, 1); MBAR_INIT(sb + 24, 1); }
    __syncthreads();
    uint32_t tmem;
    asm volatile("ld.shared.b32 %0, [%1];" : "=r"(tmem) : "r"(sb + 0));

    int r0 = tid >> 3, g = tid & 7;

    auto load_chunk = [&](int i) {
        uint32_t stage = sb + GEMM_HDR + (i & 1) * STAGE_BYTES;
        int tap = i / kchunks, kc = i - tap * kchunks;
        int shift = (tap / 3 - 1) * Wp + (tap % 3 - 1);
        const __nv_bfloat16* ah = Whi + (size_t)(tap * Cout + co_base) * Cin + kc * 64;
        const __nv_bfloat16* al = Wlo + (size_t)(tap * Cout + co_base) * Cin + kc * 64;
        const __nv_bfloat16* bh = Xhi + (size_t)(px_base + shift) * Cin + kc * 64;
        const __nv_bfloat16* bl = Xlo + (size_t)(px_base + shift) * Cin + kc * 64;
#pragma unroll
        for (int j = 0; j < 8; j++) {
            int row = r0 + 16 * j;
            uint32_t d = SWZ((uint32_t)(row * 128 + g * 16));
            cp16(stage + 0     + d, ah + (size_t)row * Cin + g * 8);
            cp16(stage + 16384 + d, al + (size_t)row * Cin + g * 8);
        }
#pragma unroll
        for (int j = 0; j < 16; j++) {
            int row = r0 + 16 * j;
            uint32_t d = SWZ((uint32_t)(row * 128 + g * 16));
            cp16(stage + 32768 + d, bh + (size_t)row * Cin + g * 8);
            cp16(stage + 65536 + d, bl + (size_t)row * Cin + g * 8);
        }
        asm volatile("cp.async.commit_group;" ::: "memory");
    };

    load_chunk(0);
    for (int i = 0; i < n_chunks; i++) {
        if (i + 1 < n_chunks) {
            if (i >= 1) MBAR_WAIT(sb + 16 + 8 * ((i + 1) & 1), ((i - 1) >> 1) & 1);
            load_chunk(i + 1);
            asm volatile("cp.async.wait_group 1;" ::: "memory");
        } else {
            asm volatile("cp.async.wait_group 0;" ::: "memory");
        }
        __syncthreads();
        if (wid == 0 && elect_one()) {
            FENCE_ASYNC();
            uint32_t stage = sb + GEMM_HDR + (i & 1) * STAGE_BYTES;
            uint64_t dAh = MK_DESC(stage), dAl = MK_DESC(stage + 16384);
            uint64_t dBh = MK_DESC(stage + 32768), dBl = MK_DESC(stage + 65536);
#pragma unroll
            for (int k = 0; k < 4; k++)
                mma_ss(tmem, dAh + 2 * k, dBh + 2 * k, MMA_IDESC, (i != 0 || k != 0) ? 1u : 0u);
#pragma unroll
            for (int k = 0; k < 4; k++)
                mma_ss(tmem, dAl + 2 * k, dBh + 2 * k, MMA_IDESC, 1u);
#pragma unroll
            for (int k = 0; k < 4; k++)
                mma_ss(tmem, dAh + 2 * k, dBl + 2 * k, MMA_IDESC, 1u);
            TC_COMMIT(sb + 16 + 8 * (i & 1));
        }
    }
    {
        int uses0 = (n_chunks + 1) >> 1, uses1 = n_chunks >> 1;
        MBAR_WAIT(sb + 16, (uses0 - 1) & 1);
        if (uses1 > 0) MBAR_WAIT(sb + 24, (uses1 - 1) & 1);
    }
    TC_FENCE_AFTER();

    // ---- epilogue: smem 32x32 transpose per warp -> coalesced NCHW stores ----
    float* tsm = reinterpret_cast<float*>(smem + GEMM_HDR) + wid * (32 * 33);
    int HW = H * W;
    float bl_lane = (co_base + wid * 32 + lane < Cout) ? bias[co_base + wid * 32 + lane] : 0.f;
    for (int cb2 = 0; cb2 < 8; cb2++) {
        uint32_t regs[32];
        TC_LD_X32(regs, tmem + cb2 * 32);
        TC_WAIT_LD();
#pragma unroll
        for (int c = 0; c < 32; c++) tsm[c * 33 + lane] = __uint_as_float(regs[c]);
        __syncwarp();
        int p = px_base + cb2 * 32 + lane;
        int valid = 0; size_t obase = 0;
        if (p < Np) {
            int n = p / HpWp; int rem = p - n * HpWp;
            int yp = rem / Wp; int xp = rem - yp * Wp;
            if ((unsigned)(yp - 1) < (unsigned)H && (unsigned)(xp - 1) < (unsigned)W) {
                valid = 1;
                obase = ((size_t)n * Cout * H + (yp - 1)) * W + (xp - 1);
            }
        }
#pragma unroll
        for (int r = 0; r < 32; r++) {
            int co = co_base + wid * 32 + r;
            float bv = __shfl_sync(0xFFFFFFFFu, bl_lane, r);
            if (co < Cout && valid) {
                float v = tsm[lane * 33 + r] + bv;
                size_t o = obase + (size_t)co * HW;
                if (skip) v += skip[o];
                if (do_lrelu) v = v > 0.f ? v : 0.2f * v;
                out[o] = v;
            }
        }
        __syncwarp();
    }
    TC_FENCE_BEFORE();
    __syncthreads();
    if (tid == 0) { MBAR_INVAL(sb + 16); MBAR_INVAL(sb + 24); }
    __syncthreads();
    if (wid == 0) TC_DEALLOC(tmem, 256);
#endif // HAS_TCGEN05
}

// ---------------- fp32 helper kernels ----------------
__global__ void ws_kernel(const float* __restrict__ w, float* __restrict__ out, int K)
{
    int f = blockIdx.x;
    const float* wf = w + (size_t)f * K;
    __shared__ float red[256];
    float s = 0.f;
    for (int i = threadIdx.x; i < K; i += 256) s += wf[i];
    red[threadIdx.x] = s; __syncthreads();
    for (int o = 128; o; o >>= 1) { if (threadIdx.x < o) red[threadIdx.x] += red[threadIdx.x + o]; __syncthreads(); }
    float mean = red[0] / (float)K;
    __syncthreads();
    float ss = 0.f;
    for (int i = threadIdx.x; i < K; i += 256) { float d = wf[i] - mean; ss += d * d; }
    red[threadIdx.x] = ss; __syncthreads();
    for (int o = 128; o; o >>= 1) { if (threadIdx.x < o) red[threadIdx.x] += red[threadIdx.x + o]; __syncthreads(); }
    float inv = 1.0f / (sqrtf(red[0] / (float)(K - 1)) + 1e-5f);
    for (int i = threadIdx.x; i < K; i += 256)
        out[(size_t)f * K + i] = (wf[i] - mean) * inv;
}

// --- GroupNorm, 3-stage deterministic ---
__global__ void gn_stats_kernel(const float* __restrict__ x, int C, int HW, int G, int S)
{
    int gid = blockIdx.x;
    int ng = gid / S, sl = gid - (gid / S) * S;
    int n = ng / G, grp = ng % G;
    int cpg = C / G;
    int len = cpg * HW;
    int slice = (len + S - 1) / S;
    int start = sl * slice;
    int end = start + slice; if (end > len) end = len;
    size_t base = ((size_t)n * C + (size_t)grp * cpg) * HW;
    __shared__ float r1[256], r2[256];
    float s = 0.f, ss = 0.f;
    for (int i = start + threadIdx.x; i < end; i += 256) {
        float v = x[base + i]; s += v; ss += v * v;
    }
    r1[threadIdx.x] = s; r2[threadIdx.x] = ss; __syncthreads();
    for (int o = 128; o; o >>= 1) {
        if (threadIdx.x < o) { r1[threadIdx.x] += r1[threadIdx.x + o]; r2[threadIdx.x] += r2[threadIdx.x + o]; }
        __syncthreads();
    }
    if (threadIdx.x == 0) { g_part[gid * 2] = r1[0]; g_part[gid * 2 + 1] = r2[0]; }
}
__global__ void gn_reduce_kernel(int S, int len)
{
    int ng = blockIdx.x;
    float s = 0.f, ss = 0.f;
    for (int i = threadIdx.x; i < S; i += 32) {
        s  += g_part[(ng * S + i) * 2];
        ss += g_part[(ng * S + i) * 2 + 1];
    }
    for (int o = 16; o; o >>= 1) {
        s  += __shfl_down_sync(0xFFFFFFFFu, s, o);
        ss += __shfl_down_sync(0xFFFFFFFFu, ss, o);
    }
    if (threadIdx.x == 0) {
        float mean = s / (float)len;
        float var  = ss / (float)len - mean * mean;
        g_mstats[ng * 2] = mean;
        g_mstats[ng * 2 + 1] = rsqrtf(var + 1e-5f);
    }
}
__global__ void gn_apply_kernel(float* __restrict__ x, const float* __restrict__ gamma,
                                const float* __restrict__ beta, int C, int HW, int G)
{
    int cpg = C / G;
    size_t total = (size_t)NB * C * HW;
    for (size_t idx = (size_t)blockIdx.x * blockDim.x + threadIdx.x; idx < total;
         idx += (size_t)gridDim.x * blockDim.x) {
        int c = (int)((idx / HW) % C);
        int n = (int)(idx / ((size_t)C * HW));
        int ng = n * G + c / cpg;
        float mean = g_mstats[ng * 2], inv = g_mstats[ng * 2 + 1];
        x[idx] = (x[idx] - mean) * inv * gamma[c] + beta[c];
    }
}

__global__ void wt_kernel(const float* __restrict__ in, float* __restrict__ out, int C, int H, int W)
{
    int h2 = H >> 1, w2 = W >> 1;
    size_t total = (size_t)NB * C * h2 * w2;
    for (size_t idx = (size_t)blockIdx.x * blockDim.x + threadIdx.x; idx < total;
         idx += (size_t)gridDim.x * blockDim.x) {
        int j = (int)(idx % w2); size_t t = idx / w2;
        int i = (int)(t % h2); t /= h2;
        int c = (int)(t % C); int n = (int)(t / C);
        const float* p = in + ((size_t)(n * C + c) * H + 2 * i) * W + 2 * j;
        float a = p[0], b = p[1], cc = p[W], d = p[W + 1];
        size_t cs = (size_t)h2 * w2;
        size_t ob = (((size_t)n * 4 * C + 4 * c) * h2 + i) * w2 + j;
        out[ob]          = 0.25f * (a + b + cc + d);
        out[ob + cs]     = 0.25f * (a + b - cc - d) + 0.5f;
        out[ob + 2 * cs] = 0.25f * (a - b + cc - d) + 0.5f;
        out[ob + 3 * cs] = 0.25f * (a - b - cc + d) + 0.5f;
    }
}

__global__ void iwt_kernel(const float* __restrict__ in, float* __restrict__ out,
                           int C, int h, int w, int c_off, int Cdst)
{
    size_t total = (size_t)NB * C * h * w;
    for (size_t idx = (size_t)blockIdx.x * blockDim.x + threadIdx.x; idx < total;
         idx += (size_t)gridDim.x * blockDim.x) {
        int j = (int)(idx % w); size_t t = idx / w;
        int i = (int)(t % h); t /= h;
        int c = (int)(t % C); int n = (int)(t / C);
        size_t cs = (size_t)h * w;
        size_t ib = (((size_t)n * 4 * C + 4 * c) * h + i) * w + j;
        float s0 = in[ib];
        float s1 = 2.f * in[ib + cs]     - 1.f;
        float s2 = 2.f * in[ib + 2 * cs] - 1.f;
        float s3 = 2.f * in[ib + 3 * cs] - 1.f;
        float* q = out + (((size_t)n * Cdst + c_off + c) * 2 * h + 2 * i) * 2 * w + 2 * j;
        q[0]         = s0 + 0.5f * ( s1 + s2 + s3);
        q[1]         = s0 + 0.5f * ( s1 - s2 - s3);
        q[2 * w]     = s0 + 0.5f * (-s1 + s2 - s3);
        q[2 * w + 1] = s0 + 0.5f * (-s1 - s2 + s3);
    }
}

__global__ void copy_ch_kernel(const float* __restrict__ src, float* __restrict__ dst,
                               int C, int HW, int Cdst, int c_off)
{
    size_t total = (size_t)NB * C * HW;
    for (size_t idx = (size_t)blockIdx.x * blockDim.x + threadIdx.x; idx < total;
         idx += (size_t)gridDim.x * blockDim.x) {
        int p = (int)(idx % HW); size_t t = idx / HW;
        int c = (int)(t % C); int n = (int)(t / C);
        dst[((size_t)n * Cdst + c_off + c) * HW + p] = src[idx];
    }
}

// fp32 direct conv, 32-co tile (for Cout > 16)
__global__ __launch_bounds__(256) void conv3x3_kernel(
    const float* __restrict__ in, const float* __restrict__ wgt,
    const float* __restrict__ bias, const float* __restrict__ skip,
    float* __restrict__ out, int Cin, int Cout, int H, int W, int do_lrelu)
{
    __shared__ __align__(16) float s_in[4][18][18];
    __shared__ __align__(16) float s_w[4][9][32];
    int tiles_x = W >> 4;
    int tx0 = (blockIdx.x % tiles_x) << 4;
    int ty0 = (blockIdx.x / tiles_x) << 4;
    int co_base = blockIdx.y << 5;
    int n = blockIdx.z;
    int tx = threadIdx.x;
    int cog8 = (tx >> 6) << 3;
    int pid  = tx & 63;
    int prow = pid >> 2;
    int pcol = (pid & 3) << 2;

    float acc[8][4];
#pragma unroll
    for (int r = 0; r < 8; r++)
#pragma unroll
        for (int p = 0; p < 4; p++) acc[r][p] = 0.f;

    for (int cc = 0; cc < Cin; cc += 4) {
        for (int idx = tx; idx < 4 * 9 * 32; idx += 256) {
            int co = idx & 31;
            int tap = (idx >> 5) % 9;
            int ci = (idx >> 5) / 9;
            float v = 0.f;
            if (co_base + co < Cout && cc + ci < Cin)
                v = wgt[((size_t)(co_base + co) * Cin + cc + ci) * 9 + tap];
            s_w[ci][tap][co] = v;
        }
        for (int idx = tx; idx < 4 * 18 * 18; idx += 256) {
            int ix = idx % 18; int t = idx / 18;
            int iy = t % 18;  int ci = t / 18;
            int gy = ty0 + iy - 1, gx = tx0 + ix - 1;
            float v = 0.f;
            if (cc + ci < Cin && gy >= 0 && gy < H && gx >= 0 && gx < W)
                v = in[((size_t)(n * Cin + cc + ci) * H + gy) * W + gx];
            s_in[ci][iy][ix] = v;
        }
        __syncthreads();
#pragma unroll
        for (int ci = 0; ci < 4; ci++)
#pragma unroll
            for (int dy = 0; dy < 3; dy++)
#pragma unroll
                for (int dx = 0; dx < 3; dx++) {
                    float xv[4];
#pragma unroll
                    for (int p = 0; p < 4; p++) xv[p] = s_in[ci][prow + dy][pcol + dx + p];
                    const float* wp = &s_w[ci][dy * 3 + dx][cog8];
                    float4 wa = *reinterpret_cast<const float4*>(wp);
                    float4 wb = *reinterpret_cast<const float4*>(wp + 4);
                    float wv[8] = {wa.x, wa.y, wa.z, wa.w, wb.x, wb.y, wb.z, wb.w};
#pragma unroll
                    for (int r = 0; r < 8; r++)
#pragma unroll
                        for (int p = 0; p < 4; p++) acc[r][p] = fmaf(wv[r], xv[p], acc[r][p]);
                }
        __syncthreads();
    }
    int oy = ty0 + prow;
#pragma unroll
    for (int r = 0; r < 8; r++) {
        int co = co_base + cog8 + r;
        if (co < Cout) {
            float b = bias ? bias[co] : 0.f;
            size_t ob = ((size_t)(n * Cout + co) * H + oy) * W + tx0 + pcol;
#pragma unroll
            for (int p = 0; p < 4; p++) {
                float v = acc[r][p] + b;
                if (skip) v += skip[ob + p];
                if (do_lrelu) v = v > 0.f ? v : 0.2f * v;
                out[ob + p] = v;
            }
        }
    }
}

// fp32 direct conv, 16-co tile (for Cout <= 16): 2 co-groups x 128 px threads
__global__ __launch_bounds__(256) void conv3x3_c16_kernel(
    const float* __restrict__ in, const float* __restrict__ wgt,
    const float* __restrict__ bias, const float* __restrict__ skip,
    float* __restrict__ out, int Cin, int Cout, int H, int W, int do_lrelu)
{
    __shared__ __align__(16) float s_in[4][18][18];
    __shared__ __align__(16) float s_w[4][9][16];
    int tiles_x = W >> 4;
    int tx0 = (blockIdx.x % tiles_x) << 4;
    int ty0 = (blockIdx.x / tiles_x) << 4;
    int n = blockIdx.z;
    int tx = threadIdx.x;
    int cog8 = (tx >> 7) << 3;      // 0 or 8
    int pid  = tx & 127;
    int prow = pid >> 3;            // 0..15
    int pcol = (pid & 7) << 1;      // 0,2,...,14

    float acc[8][2];
#pragma unroll
    for (int r = 0; r < 8; r++) { acc[r][0] = 0.f; acc[r][1] = 0.f; }

    for (int cc = 0; cc < Cin; cc += 4) {
        for (int idx = tx; idx < 4 * 9 * 16; idx += 256) {
            int co = idx & 15;
            int tap = (idx >> 4) % 9;
            int ci = (idx >> 4) / 9;
            float v = 0.f;
            if (co < Cout && cc + ci < Cin)
                v = wgt[((size_t)co * Cin + cc + ci) * 9 + tap];
            s_w[ci][tap][co] = v;
        }
        for (int idx = tx; idx < 4 * 18 * 18; idx += 256) {
            int ix = idx % 18; int t = idx / 18;
            int iy = t % 18;  int ci = t / 18;
            int gy = ty0 + iy - 1, gx = tx0 + ix - 1;
            float v = 0.f;
            if (cc + ci < Cin && gy >= 0 && gy < H && gx >= 0 && gx < W)
                v = in[((size_t)(n * Cin + cc + ci) * H + gy) * W + gx];
            s_in[ci][iy][ix] = v;
        }
        __syncthreads();
#pragma unroll
        for (int ci = 0; ci < 4; ci++)
#pragma unroll
            for (int dy = 0; dy < 3; dy++)
#pragma unroll
                for (int dx = 0; dx < 3; dx++) {
                    float x0 = s_in[ci][prow + dy][pcol + dx];
                    float x1 = s_in[ci][prow + dy][pcol + dx + 1];
                    const float* wp = &s_w[ci][dy * 3 + dx][cog8];
                    float4 wa = *reinterpret_cast<const float4*>(wp);
                    float4 wb = *reinterpret_cast<const float4*>(wp + 4);
                    float wv[8] = {wa.x, wa.y, wa.z, wa.w, wb.x, wb.y, wb.z, wb.w};
#pragma unroll
                    for (int r = 0; r < 8; r++) {
                        acc[r][0] = fmaf(wv[r], x0, acc[r][0]);
                        acc[r][1] = fmaf(wv[r], x1, acc[r][1]);
                    }
                }
        __syncthreads();
    }
    int oy = ty0 + prow;
#pragma unroll
    for (int r = 0; r < 8; r++) {
        int co = cog8 + r;
        if (co < Cout) {
            float b = bias ? bias[co] : 0.f;
            size_t ob = ((size_t)(n * Cout + co) * H + oy) * W + tx0 + pcol;
#pragma unroll
            for (int p = 0; p < 2; p++) {
                float v = acc[r][p] + b;
                if (skip) v += skip[ob + p];
                if (do_lrelu) v = v > 0.f ? v : 0.2f * v;
                out[ob + p] = v;
            }
        }
    }
}

__global__ void final_kernel(const float* __restrict__ in, const float* __restrict__ w,
                             float* __restrict__ out, int HW)
{
    size_t total = (size_t)NB * HW;
    for (size_t idx = (size_t)blockIdx.x * blockDim.x + threadIdx.x; idx < total;
         idx += (size_t)gridDim.x * blockDim.x) {
        int p = (int)(idx % HW); int n = (int)(idx / HW);
        const float* ip = in + (size_t)n * 3 * HW + p;
        float x0 = ip[0], x1 = ip[HW], x2 = ip[2 * HW];
        float* op = out + (size_t)n * 2 * HW + p;
        op[0]  = w[0] * x0 + w[1] * x1 + w[2] * x2;
        op[HW] = w[3] * x0 + w[4] * x1 + w[5] * x2;
    }
}

// ---------------- host ----------------
static inline int blocks_for(size_t n) { return (int)((n + 255) / 256); }

extern "C" void kernel_launch(void* const* d_in, const int* in_sizes, int n_in,
                              void* d_out, int out_size)
{
    const float* x        = (const float*)d_in[0];
    const float* conv1_w  = (const float*)d_in[1];  const float* conv1_b  = (const float*)d_in[2];
    const float* conv2_w  = (const float*)d_in[3];  const float* conv2_b  = (const float*)d_in[4];
    const float* conv3_w  = (const float*)d_in[5];  const float* conv3_b  = (const float*)d_in[6];
    const float* conv4_w  = (const float*)d_in[7];  const float* conv4_b  = (const float*)d_in[8];
    const float* convd1_w = (const float*)d_in[9];  const float* convd1_b = (const float*)d_in[10];
    const float* convd2_w = (const float*)d_in[11]; const float* convd2_b = (const float*)d_in[12];
    const float* convd3_w = (const float*)d_in[13]; const float* convd3_b = (const float*)d_in[14];
    const float* convd4_w = (const float*)d_in[15]; const float* convd4_b = (const float*)d_in[16];
    const float* final_w  = (const float*)d_in[17];
    const float* gn1_w = (const float*)d_in[18]; const float* gn1_b = (const float*)d_in[19];
    const float* gn2_w = (const float*)d_in[20]; const float* gn2_b = (const float*)d_in[21];
    const float* gn3_w = (const float*)d_in[22]; const float* gn3_b = (const float*)d_in[23];
    const float* gn4_w = (const float*)d_in[24]; const float* gn4_b = (const float*)d_in[25];

    float *c1, *c2, *c3, *w4, *t0, *t1, *big, *wsw;
    __nv_bfloat16 *xhi, *xlo, *whi, *wlo;
    cudaGetSymbolAddress((void**)&c1,  g_c1);
    cudaGetSymbolAddress((void**)&c2,  g_c2);
    cudaGetSymbolAddress((void**)&c3,  g_c3);
    cudaGetSymbolAddress((void**)&w4,  g_w4);
    cudaGetSymbolAddress((void**)&t0,  g_t0);
    cudaGetSymbolAddress((void**)&t1,  g_t1);
    cudaGetSymbolAddress((void**)&big, g_big);
    cudaGetSymbolAddress((void**)&wsw, g_wsw);
    cudaGetSymbolAddress((void**)&xhi, g_xhi);
    cudaGetSymbolAddress((void**)&xlo, g_xlo);
    cudaGetSymbolAddress((void**)&whi, g_whi);
    cudaGetSymbolAddress((void**)&wlo, g_wlo);

    cudaFuncSetAttribute(conv_mma_kernel, cudaFuncAttributeMaxDynamicSharedMemorySize, GEMM_SMEM);

    auto ntiles_of = [](int H, int W) { return (NB * (H + 2) * (W + 2) + 255) / 256; };
    auto prep_w = [&](const float* w, int Cin, int Cout) {
        ws_kernel<<<Cout, 256>>>(w, wsw, Cin * 9);
        pack_w_kernel<<<blocks_for((size_t)9 * Cout * Cin), 256>>>(wsw, whi, wlo, Cout, Cin);
    };
    auto clear_x = [&](int Cin, int H, int W) {
        size_t xb = (size_t)(2 * PADPIX + ntiles_of(H, W) * 256) * Cin * sizeof(__nv_bfloat16);
        cudaMemsetAsync(xhi, 0, xb);
        cudaMemsetAsync(xlo, 0, xb);
    };
    auto run_mma = [&](const float* b, const float* skip, float* out,
                       int Cin, int Cout, int H, int W) {
        dim3 g(ntiles_of(H, W), (Cout + 127) / 128);
        conv_mma_kernel<<<g, 128, GEMM_SMEM>>>(whi, wlo, xhi + (size_t)PADPIX * Cin,
                                               xlo + (size_t)PADPIX * Cin, b, skip, out,
                                               Cin, Cout, H, W, 1);
    };
    auto gn = [&](float* xp, const float* gw, const float* gb, int C, int HW, int G) {
        int NG = NB * G;
        int S = 2048 / NG; if (S < 1) S = 1; if (S > 32) S = 32;
        int cpg = C / G;
        gn_stats_kernel<<<NG * S, 256>>>(xp, C, HW, G, S);
        gn_reduce_kernel<<<NG, 32>>>(S, cpg * HW);
        gn_apply_kernel<<<2048, 256>>>(xp, gw, gb, C, HW, G);
    };

    // ---------------- encoder ----------------
    // w1 = wt(x) fp32 only (feeds small fp32 conv1)
    wt_kernel<<<blocks_for((size_t)NB * 3 * 128 * 128), 256>>>(x, t0, 3, 256, 256);
    ws_kernel<<<16, 256>>>(conv1_w, wsw, 12 * 9);
    conv3x3_c16_kernel<<<dim3(64, 1, NB), 256>>>(t0, wsw, conv1_b, nullptr, c1, 12, 16, 128, 128, 1);
    gn(c1, gn1_w, gn1_b, 16, 128 * 128, 2);

    // conv2: fused wt+pack from c1
    prep_w(conv2_w, 64, 64);
    clear_x(64, 64, 64);
    wt_pack_kernel<<<blocks_for((size_t)NB * 16 * 64 * 64), 256>>>(
        c1, nullptr, xhi + (size_t)PADPIX * 64, xlo + (size_t)PADPIX * 64, 16, 128, 128);
    run_mma(conv2_b, nullptr, c2, 64, 64, 64, 64);
    gn(c2, gn2_w, gn2_b, 64, 64 * 64, 8);

    // conv3
    prep_w(conv3_w, 256, 256);
    clear_x(256, 32, 32);
    wt_pack_kernel<<<blocks_for((size_t)NB * 64 * 32 * 32), 256>>>(
        c2, nullptr, xhi + (size_t)PADPIX * 256, xlo + (size_t)PADPIX * 256, 64, 64, 64);
    run_mma(conv3_b, nullptr, c3, 256, 256, 32, 32);
    gn(c3, gn3_w, gn3_b, 256, 32 * 32, 32);

    // conv4 x3 (weights packed ONCE)
    prep_w(conv4_w, 1024, 1024);
    clear_x(1024, 16, 16);
    wt_pack_kernel<<<blocks_for((size_t)NB * 256 * 16 * 16), 256>>>(
        c3, w4, xhi + (size_t)PADPIX * 1024, xlo + (size_t)PADPIX * 1024, 256, 32, 32);
    run_mma(conv4_b, nullptr, t0, 1024, 1024, 16, 16);
    gn(t0, gn4_w, gn4_b, 1024, 16 * 16, 128);

    clear_x(1024, 16, 16);
    pack_x_kernel<<<blocks_for((size_t)NB * 16 * 16 * 1024), 256>>>(
        t0, xhi + (size_t)PADPIX * 1024, xlo + (size_t)PADPIX * 1024, 1024, 16, 16);
    run_mma(conv4_b, nullptr, t1, 1024, 1024, 16, 16);
    gn(t1, gn4_w, gn4_b, 1024, 16 * 16, 128);

    clear_x(1024, 16, 16);
    pack_x_kernel<<<blocks_for((size_t)NB * 16 * 16 * 1024), 256>>>(
        t1, xhi + (size_t)PADPIX * 1024, xlo + (size_t)PADPIX * 1024, 1024, 16, 16);
    run_mma(conv4_b, w4, t0, 1024, 1024, 16, 16);   // ic4 = lrelu(conv + w4)

    // ---------------- decoder ----------------
    // convd4: iw4 = concat([c3, iwt(ic4)])
    iwt_kernel<<<blocks_for((size_t)NB * 256 * 16 * 16), 256>>>(t0, big, 256, 16, 16, 256, 512);
    copy_ch_kernel<<<blocks_for((size_t)NB * 256 * 1024), 256>>>(c3, big, 256, 32 * 32, 512, 0);
    prep_w(convd4_w, 512, 256);
    clear_x(512, 32, 32);
    pack_x_kernel<<<blocks_for((size_t)NB * 32 * 32 * 512), 256>>>(
        big, xhi + (size_t)PADPIX * 512, xlo + (size_t)PADPIX * 512, 512, 32, 32);
    run_mma(convd4_b, nullptr, t1, 512, 256, 32, 32);
    gn(t1, gn3_w, gn3_b, 256, 32 * 32, 32);   // ic3

    // convd3
    iwt_kernel<<<blocks_for((size_t)NB * 64 * 32 * 32), 256>>>(t1, big, 64, 32, 32, 64, 128);
    copy_ch_kernel<<<blocks_for((size_t)NB * 64 * 4096), 256>>>(c2, big, 64, 64 * 64, 128, 0);
    prep_w(convd3_w, 128, 64);
    clear_x(128, 64, 64);
    pack_x_kernel<<<blocks_for((size_t)NB * 64 * 64 * 128), 256>>>(
        big, xhi + (size_t)PADPIX * 128, xlo + (size_t)PADPIX * 128, 128, 64, 64);
    run_mma(convd3_b, nullptr, t0, 128, 64, 64, 64);
    gn(t0, gn2_w, gn2_b, 64, 64 * 64, 8);     // ic2

    // level2: fp32 path
    iwt_kernel<<<blocks_for((size_t)NB * 16 * 64 * 64), 256>>>(t0, big, 16, 64, 64, 16, 32);
    copy_ch_kernel<<<blocks_for((size_t)NB * 16 * 16384), 256>>>(c1, big, 16, 128 * 128, 32, 0);
    ws_kernel<<<16, 256>>>(convd2_w, wsw, 32 * 9);
    conv3x3_c16_kernel<<<dim3(64, 1, NB), 256>>>(big, wsw, convd2_b, nullptr, t1, 32, 16, 128, 128, 1);
    gn(t1, gn1_w, gn1_b, 16, 128 * 128, 2);   // ic1

    ws_kernel<<<12, 256>>>(convd1_w, wsw, 16 * 9);
    conv3x3_c16_kernel<<<dim3(64, 1, NB), 256>>>(t1, wsw, convd1_b, nullptr, t0, 16, 12, 128, 128, 1);

    iwt_kernel<<<blocks_for((size_t)NB * 3 * 128 * 128), 256>>>(t0, t1, 3, 128, 128, 0, 3);
    ws_kernel<<<2, 256>>>(final_w, wsw, 3);
    final_kernel<<<blocks_for((size_t)NB * 256 * 256), 256>>>(t1, wsw, (float*)d_out, 256 * 256);
}